// round 14
// baseline (speedup 1.0000x reference)
#include <cuda_runtime.h>
#include <cuda_fp16.h>
#include <cstdint>
#include <cstring>

#define N_NODES 50000
#define N_EDGES 800000
#define IN_CH   64
#define HID_CH  128

#define NWARP 4          // warps per fused block
#define NPB   16         // nodes per fused block (4 per warp)
#define CAP   96         // bucket capacity (deg ~ Poisson(16))
#define NPAD  (N_NODES + NPB)
#define STAGE 16         // edges per cp.async stage (2KB group in fp16)

// Scratch (device globals; zero-initialized at load).
// Invariant: g_cnt == 0 at entry of every kernel_launch (k_fused resets it).
__device__ int   g_cnt[NPAD];
__device__ int   g_esrc[NPAD * CAP];
__device__ uint4 g_xh[N_NODES * IN_CH / 8];   // fp16 copy of x (6.4MB), 128B/row

// packed f32x2 FMA: d = a*b + d
__device__ __forceinline__ void fma2(unsigned long long& d,
                                     unsigned long long a,
                                     unsigned long long b) {
    asm("fma.rn.f32x2 %0, %1, %2, %0;" : "+l"(d) : "l"(a), "l"(b));
}
__device__ __forceinline__ void cp16(uint32_t smem_addr, const void* gptr) {
    asm volatile("cp.async.cg.shared.global [%0], [%1], 16;"
                 :: "r"(smem_addr), "l"(gptr) : "memory");
}
__device__ __forceinline__ void cp_commit() {
    asm volatile("cp.async.commit_group;" ::: "memory");
}
template <int N>
__device__ __forceinline__ void cp_wait() {
    asm volatile("cp.async.wait_group %0;" :: "n"(N) : "memory");
}
__device__ __forceinline__ __half2 u2h2(unsigned u) {
    __half2 h; memcpy(&h, &u, 4); return h;
}
__device__ __forceinline__ unsigned h2u(__half2 h) {
    unsigned u; memcpy(&u, &h, 4); return u;
}

// ---------------------------------------------------------------------------
// 0) convert x (fp32) -> g_xh (fp16). 400k uint4 stores.
// ---------------------------------------------------------------------------
__global__ void k_cvt(const float* __restrict__ x) {
    int i = blockIdx.x * blockDim.x + threadIdx.x;
    const int total = N_NODES * IN_CH / 8;
    if (i >= total) return;
    float4 a = __ldg(reinterpret_cast<const float4*>(x) + 2 * i);
    float4 b = __ldg(reinterpret_cast<const float4*>(x) + 2 * i + 1);
    uint4 o;
    o.x = h2u(__floats2half2_rn(a.x, a.y));
    o.y = h2u(__floats2half2_rn(a.z, a.w));
    o.z = h2u(__floats2half2_rn(b.x, b.y));
    o.w = h2u(__floats2half2_rn(b.z, b.w));
    g_xh[i] = o;
}

// ---------------------------------------------------------------------------
// 1) bucket edges by dst
// ---------------------------------------------------------------------------
__global__ void k_bucket(const int* __restrict__ ei) {
    int e = blockIdx.x * blockDim.x + threadIdx.x;
    if (e >= N_EDGES) return;
    int src = ei[e];
    int dst = ei[N_EDGES + e];
    if ((unsigned)src >= N_NODES || (unsigned)dst >= N_NODES) return;
    int pos = atomicAdd(&g_cnt[dst], 1);
    if (pos < CAP) g_esrc[dst * CAP + pos] = src;
}

// ---------------------------------------------------------------------------
// 2) fused aggregate (mean, fp16 gather -> fp32 accum) + GEMM + counter reset.
// Block = 128 thr = 4 warps, 16 nodes (4/warp).
// Lane map: c8 = lane&7 (16B chunk of the 128B fp16 row), q = lane>>3
//   (edge slot parity, 4 edges in flight per cp round).
// Phase A: double-buffered cp.async pipeline, STAGE=16 edges (2KB group),
//   wait_group<1>. Consume converts fp16->fp32 and accumulates 8 channels
//   per lane; cross-q reduce via 2 shfl rounds.
// Phase B: out[n][o] = mean[n].W[o] via packed f32x2 FMAs (o = tid).
// ---------------------------------------------------------------------------
__global__ void __launch_bounds__(128, 6)
k_fused(const float* __restrict__ W, float* __restrict__ out) {
    __shared__ uint4 s_buf[NWARP][2][STAGE][8];      // 16 KB
    __shared__ float s_mean[NPB * IN_CH];            // 4 KB
    __shared__ int   s_cnt[NPB];

    const int tid   = threadIdx.x;
    const int node0 = blockIdx.x * NPB;
    const int wid   = tid >> 5;
    const int lane  = tid & 31;
    const int c8    = lane & 7;
    const int q     = lane >> 3;

    // read-once-then-zero: single owner per counter, published via smem
    if (tid < NPB) {
        int v = g_cnt[node0 + tid];
        s_cnt[tid] = v;
        g_cnt[node0 + tid] = 0;
    }
    __syncthreads();

    // accumulators: 4 nodes x 8 fp32 channels (lo = ch 0-3, hi = ch 4-7 of chunk)
    float4 a0l = {0,0,0,0}, a0h = {0,0,0,0}, a1l = {0,0,0,0}, a1h = {0,0,0,0};
    float4 a2l = {0,0,0,0}, a2h = {0,0,0,0}, a3l = {0,0,0,0}, a3h = {0,0,0,0};

    // pending-stage state (warp-uniform)
    int pk = -1, pcnt = 0, pbuf = 0, p = 0;

    #define ACCV(LO, HI, V)                                                    \
        do {                                                                   \
            float2 f0 = __half22float2(u2h2((V).x));                           \
            float2 f1 = __half22float2(u2h2((V).y));                           \
            float2 f2 = __half22float2(u2h2((V).z));                           \
            float2 f3 = __half22float2(u2h2((V).w));                           \
            LO.x += f0.x; LO.y += f0.y; LO.z += f1.x; LO.w += f1.y;            \
            HI.x += f2.x; HI.y += f2.y; HI.z += f3.x; HI.w += f3.y;            \
        } while (0)

    #define CONSUME(PBUF, PCNT, PK)                                            \
        do {                                                                   \
            _Pragma("unroll")                                                  \
            for (int r = 0; r < 4; r++) {                                      \
                int slot = 4 * r + q;                                          \
                if (slot < (PCNT)) {                                           \
                    uint4 v = s_buf[wid][PBUF][slot][c8];                      \
                    if      ((PK) == 0) ACCV(a0l, a0h, v);                     \
                    else if ((PK) == 1) ACCV(a1l, a1h, v);                     \
                    else if ((PK) == 2) ACCV(a2l, a2h, v);                     \
                    else                ACCV(a3l, a3h, v);                     \
                }                                                              \
            }                                                                  \
        } while (0)

    for (int k = 0; k < 4; k++) {
        const int ln   = wid * 4 + k;             // local node (0..15)
        const int cnt  = s_cnt[ln];
        const int m    = min(cnt, CAP);
        const int base = (node0 + ln) * CAP;

        for (int w = 0; w < m; w += 32) {
            const int mw  = min(m - w, 32);
            int idx = ((w + lane) < m) ? g_esrc[base + w + lane] : 0;
            const int nst = (mw + STAGE - 1) / STAGE;   // 1 or 2

            for (int s = 0; s < nst; s++) {
                __syncwarp();                     // WAR guard on buffer p
                #pragma unroll
                for (int r = 0; r < 4; r++) {
                    const int slot = 4 * r + q;
                    const int eL   = s * STAGE + slot;   // <= 31
                    int src = __shfl_sync(0xffffffffu, idx, eL & 31);
                    if (eL < mw) {
                        uint32_t dstw = (uint32_t)__cvta_generic_to_shared(
                            &s_buf[wid][p][slot][c8]);
                        cp16(dstw, g_xh + (size_t)src * 8 + c8);
                    }
                }
                cp_commit();

                if (pk >= 0) {                    // consume previous group
                    cp_wait<1>();
                    __syncwarp();
                    CONSUME(pbuf, pcnt, pk);
                }
                pk = k; pcnt = min(mw - s * STAGE, STAGE); pbuf = p; p ^= 1;
            }
        }
    }
    if (pk >= 0) {                                // drain last group
        cp_wait<0>();
        __syncwarp();
        CONSUME(pbuf, pcnt, pk);
    }

    // cross-q reduce (q0 += q1+q2+q3) + mean -> smem
    #define FINALIZE(LO, HI, K)                                                \
        do {                                                                   \
            LO.x += __shfl_down_sync(0xffffffffu, LO.x, 16);                   \
            LO.y += __shfl_down_sync(0xffffffffu, LO.y, 16);                   \
            LO.z += __shfl_down_sync(0xffffffffu, LO.z, 16);                   \
            LO.w += __shfl_down_sync(0xffffffffu, LO.w, 16);                   \
            HI.x += __shfl_down_sync(0xffffffffu, HI.x, 16);                   \
            HI.y += __shfl_down_sync(0xffffffffu, HI.y, 16);                   \
            HI.z += __shfl_down_sync(0xffffffffu, HI.z, 16);                   \
            HI.w += __shfl_down_sync(0xffffffffu, HI.w, 16);                   \
            LO.x += __shfl_down_sync(0xffffffffu, LO.x, 8);                    \
            LO.y += __shfl_down_sync(0xffffffffu, LO.y, 8);                    \
            LO.z += __shfl_down_sync(0xffffffffu, LO.z, 8);                    \
            LO.w += __shfl_down_sync(0xffffffffu, LO.w, 8);                    \
            HI.x += __shfl_down_sync(0xffffffffu, HI.x, 8);                    \
            HI.y += __shfl_down_sync(0xffffffffu, HI.y, 8);                    \
            HI.z += __shfl_down_sync(0xffffffffu, HI.z, 8);                    \
            HI.w += __shfl_down_sync(0xffffffffu, HI.w, 8);                    \
            if (q == 0) {                                                      \
                int ln2 = wid * 4 + (K);                                       \
                float scl = 1.0f / fmaxf((float)s_cnt[ln2], 1.0f);             \
                float* dst = &s_mean[ln2 * IN_CH + c8 * 8];                    \
                *reinterpret_cast<float4*>(dst) =                              \
                    make_float4(LO.x*scl, LO.y*scl, LO.z*scl, LO.w*scl);       \
                *reinterpret_cast<float4*>(dst + 4) =                          \
                    make_float4(HI.x*scl, HI.y*scl, HI.z*scl, HI.w*scl);       \
            }                                                                  \
        } while (0)
    FINALIZE(a0l, a0h, 0);
    FINALIZE(a1l, a1h, 1);
    FINALIZE(a2l, a2h, 2);
    FINALIZE(a3l, a3h, 3);

    // W row -> 32 packed f32x2 registers (after the gather phase)
    const int o = tid;                            // 128 output channels
    unsigned long long w2[IN_CH / 2];
    {
        const ulonglong2* Wrow = reinterpret_cast<const ulonglong2*>(W) + o * (IN_CH / 4);
        #pragma unroll
        for (int kk = 0; kk < IN_CH / 4; kk++) {
            ulonglong2 t = __ldg(Wrow + kk);
            w2[2 * kk + 0] = t.x;
            w2[2 * kk + 1] = t.y;
        }
    }
    __syncthreads();

    // Phase B: GEMM — each thread computes its channel o for all 16 nodes
    #pragma unroll 4
    for (int n = 0; n < NPB; n++) {
        unsigned long long a2 = 0ull;
        const ulonglong2* mrow = reinterpret_cast<const ulonglong2*>(s_mean + n * IN_CH);
        #pragma unroll
        for (int kk = 0; kk < IN_CH / 4; kk++) {
            ulonglong2 mv = mrow[kk];             // LDS.128, broadcast
            fma2(a2, mv.x, w2[2 * kk + 0]);
            fma2(a2, mv.y, w2[2 * kk + 1]);
        }
        float lo, hi;
        asm("mov.b64 {%0, %1}, %2;" : "=f"(lo), "=f"(hi) : "l"(a2));
        const int node = node0 + n;
        if (node < N_NODES) {
            out[(size_t)node * HID_CH + o] = lo + hi;
        }
    }
}

// ---------------------------------------------------------------------------
extern "C" void kernel_launch(void* const* d_in, const int* in_sizes, int n_in,
                              void* d_out, int out_size) {
    const float* x  = (const float*)d_in[0];      // [50000, 64] fp32
    const int*   ei = (const int*)d_in[1];        // [2, 800000] int32
    const float* W  = (const float*)d_in[2];      // [128, 64] fp32
    float* out = (float*)d_out;                   // [50000, 128] fp32

    k_cvt<<<(N_NODES * IN_CH / 8 + 255) / 256, 256>>>(x);
    k_bucket<<<(N_EDGES + 255) / 256, 256>>>(ei);
    k_fused<<<(N_NODES + NPB - 1) / NPB, 128>>>(W, out);
}

// round 15
// speedup vs baseline: 1.0024x; 1.0024x over previous
#include <cuda_runtime.h>
#include <cstdint>

#define N_NODES 50000
#define N_EDGES 800000
#define IN_CH   64
#define HID_CH  128

#define NWARP 4          // warps per fused block
#define NPB   16         // nodes per fused block (4 per warp)
#define CAP   96         // bucket capacity (deg ~ Poisson(16))
#define NPAD  (N_NODES + NPB)
#define WIN   16         // edges per TMA window (4KB)

// Scratch (device globals; zero-initialized at load).
// Invariant: g_cnt == 0 at entry of every kernel_launch (k_fused resets it).
__device__ int g_cnt[NPAD];
__device__ int g_esrc[NPAD * CAP];

// packed f32x2 FMA: d = a*b + d
__device__ __forceinline__ void fma2(unsigned long long& d,
                                     unsigned long long a,
                                     unsigned long long b) {
    asm("fma.rn.f32x2 %0, %1, %2, %0;" : "+l"(d) : "l"(a), "l"(b));
}
__device__ __forceinline__ uint32_t smem_u32(const void* p) {
    return (uint32_t)__cvta_generic_to_shared(p);
}
__device__ __forceinline__ void mbar_init(uint32_t mbar, unsigned count) {
    asm volatile("mbarrier.init.shared.b64 [%0], %1;" :: "r"(mbar), "r"(count) : "memory");
}
__device__ __forceinline__ void mbar_expect_tx(uint32_t mbar, unsigned bytes) {
    asm volatile("mbarrier.arrive.expect_tx.shared.b64 _, [%0], %1;"
                 :: "r"(mbar), "r"(bytes) : "memory");
}
__device__ __forceinline__ void mbar_wait(uint32_t mbar, unsigned phase) {
    asm volatile(
        "{\n\t.reg .pred P;\n\t"
        "WAIT_%=:\n\t"
        "mbarrier.try_wait.parity.acquire.cta.shared::cta.b64 P, [%0], %1;\n\t"
        "@!P bra WAIT_%=;\n\t"
        "}"
        :: "r"(mbar), "r"(phase) : "memory");
}
// one 256B row: global -> smem via bulk-copy engine, completion on mbar
__device__ __forceinline__ void bulk_row(uint32_t dst_smem, const void* src,
                                         uint32_t mbar) {
    asm volatile(
        "cp.async.bulk.shared::cluster.global.mbarrier::complete_tx::bytes "
        "[%0], [%1], %2, [%3];"
        :: "r"(dst_smem), "l"(src), "r"(256u), "r"(mbar) : "memory");
}

// ---------------------------------------------------------------------------
// 1) bucket edges by dst
// ---------------------------------------------------------------------------
__global__ void k_bucket(const int* __restrict__ ei) {
    int e = blockIdx.x * blockDim.x + threadIdx.x;
    if (e >= N_EDGES) return;
    int src = ei[e];
    int dst = ei[N_EDGES + e];
    if ((unsigned)src >= N_NODES || (unsigned)dst >= N_NODES) return;
    int pos = atomicAdd(&g_cnt[dst], 1);
    if (pos < CAP) g_esrc[dst * CAP + pos] = src;
}

// ---------------------------------------------------------------------------
// 2) fused aggregate (mean) + GEMM + counter reset.
// Block = 128 thr = 4 warps, 16 nodes (4/warp).
// Phase A: per warp, windows of <=16 edges. Lane e (<mw) loads its OWN edge
//   index (coalesced) and issues ONE cp.async.bulk of the full 256B row into
//   s_buf[wid][p][e] — no per-chunk cp loop, no shuffles. Completion via a
//   per-(warp,buffer) mbarrier (expect_tx = mw*256). Double-buffered:
//   window i+1 is issued before window i is consumed.
// Consume: lane (c = lane&15 chunk, q = lane>>4): slots 2r+q, fp32 adds;
//   cross-q shfl reduce; mean -> s_mean.
// Phase B: out[n][o] = mean[n].W[o] via packed f32x2 FMAs (o = tid).
// ---------------------------------------------------------------------------
__global__ void __launch_bounds__(128, 6)
k_fused(const float* __restrict__ x, const float* __restrict__ W,
        float* __restrict__ out) {
    __shared__ float4 s_buf[NWARP][2][WIN][IN_CH / 4];   // 32 KB
    __shared__ float  s_mean[NPB * IN_CH];               // 4 KB
    __shared__ int    s_cnt[NPB];
    __shared__ __align__(8) unsigned long long s_mbar[NWARP][2];

    const int tid   = threadIdx.x;
    const int node0 = blockIdx.x * NPB;
    const int wid   = tid >> 5;
    const int lane  = tid & 31;
    const int c     = lane & 15;     // float4 chunk of the 256B row
    const int q     = lane >> 4;     // edge-slot parity

    // read-once-then-zero counters (race-free via smem publish)
    if (tid < NPB) {
        int v = g_cnt[node0 + tid];
        s_cnt[tid] = v;
        g_cnt[node0 + tid] = 0;
    }
    if (lane == 0) {
        mbar_init(smem_u32(&s_mbar[wid][0]), 1);
        mbar_init(smem_u32(&s_mbar[wid][1]), 1);
    }
    __syncthreads();

    float4 a0 = {0,0,0,0}, a1 = {0,0,0,0}, a2v = {0,0,0,0}, a3 = {0,0,0,0};

    // pending-window state (warp-uniform). ph0/ph1: parity per buffer.
    int pk = -1, pcnt = 0, pbuf = 0, p = 0, ph0 = 0, ph1 = 0;

    #define CONSUME(PBUF, PCNT, PK)                                            \
        do {                                                                   \
            float4 part = {0,0,0,0};                                           \
            _Pragma("unroll")                                                  \
            for (int r = 0; r < WIN / 2; r++) {                                \
                int slot = 2 * r + q;                                          \
                if (slot < (PCNT)) {                                           \
                    float4 v = s_buf[wid][PBUF][slot][c];                      \
                    part.x += v.x; part.y += v.y;                              \
                    part.z += v.z; part.w += v.w;                              \
                }                                                              \
            }                                                                  \
            if      ((PK) == 0) { a0.x+=part.x;  a0.y+=part.y;  a0.z+=part.z;  a0.w+=part.w;  } \
            else if ((PK) == 1) { a1.x+=part.x;  a1.y+=part.y;  a1.z+=part.z;  a1.w+=part.w;  } \
            else if ((PK) == 2) { a2v.x+=part.x; a2v.y+=part.y; a2v.z+=part.z; a2v.w+=part.w; } \
            else                { a3.x+=part.x;  a3.y+=part.y;  a3.z+=part.z;  a3.w+=part.w;  } \
        } while (0)

    #define WAIT_PENDING()                                                     \
        do {                                                                   \
            uint32_t mb = smem_u32(&s_mbar[wid][pbuf]);                        \
            int phv = pbuf ? ph1 : ph0;                                        \
            mbar_wait(mb, (unsigned)phv);                                      \
            if (pbuf) ph1 ^= 1; else ph0 ^= 1;                                 \
        } while (0)

    for (int k = 0; k < 4; k++) {
        const int ln   = wid * 4 + k;             // local node (0..15)
        const int cnt  = s_cnt[ln];
        const int m    = min(cnt, CAP);
        const int base = (node0 + ln) * CAP;

        for (int w = 0; w < m; w += WIN) {
            const int mw = min(m - w, WIN);
            // issue window into buffer p (1 expect_tx + <=16 bulk copies)
            uint32_t mb_p = smem_u32(&s_mbar[wid][p]);
            if (lane == 0) mbar_expect_tx(mb_p, (unsigned)(mw * 256));
            if (lane < mw) {
                int idx = g_esrc[base + w + lane];
                bulk_row(smem_u32(&s_buf[wid][p][lane][0]),
                         x + (size_t)idx * IN_CH, mb_p);
            }
            // consume previous window (buffer p^1) while this one flies
            if (pk >= 0) {
                WAIT_PENDING();
                CONSUME(pbuf, pcnt, pk);
            }
            pk = k; pcnt = mw; pbuf = p; p ^= 1;
        }
    }
    if (pk >= 0) {                                // drain last window
        WAIT_PENDING();
        CONSUME(pbuf, pcnt, pk);
    }

    // cross-q reduce + mean -> smem
    #define FINALIZE(A, K)                                                     \
        do {                                                                   \
            A.x += __shfl_down_sync(0xffffffffu, A.x, 16);                     \
            A.y += __shfl_down_sync(0xffffffffu, A.y, 16);                     \
            A.z += __shfl_down_sync(0xffffffffu, A.z, 16);                     \
            A.w += __shfl_down_sync(0xffffffffu, A.w, 16);                     \
            if (q == 0) {                                                      \
                int ln2 = wid * 4 + (K);                                       \
                float scl = 1.0f / fmaxf((float)s_cnt[ln2], 1.0f);             \
                *reinterpret_cast<float4*>(&s_mean[ln2 * IN_CH + c * 4]) =     \
                    make_float4(A.x * scl, A.y * scl, A.z * scl, A.w * scl);   \
            }                                                                  \
        } while (0)
    FINALIZE(a0, 0);
    FINALIZE(a1, 1);
    FINALIZE(a2v, 2);
    FINALIZE(a3, 3);

    // W row -> 32 packed f32x2 registers
    const int o = tid;                            // 128 output channels
    unsigned long long w2[IN_CH / 2];
    {
        const ulonglong2* Wrow = reinterpret_cast<const ulonglong2*>(W) + o * (IN_CH / 4);
        #pragma unroll
        for (int kk = 0; kk < IN_CH / 4; kk++) {
            ulonglong2 t = __ldg(Wrow + kk);
            w2[2 * kk + 0] = t.x;
            w2[2 * kk + 1] = t.y;
        }
    }
    __syncthreads();

    // Phase B: GEMM — each thread computes its channel o for all 16 nodes
    #pragma unroll 4
    for (int n = 0; n < NPB; n++) {
        unsigned long long acc2 = 0ull;
        const ulonglong2* mrow = reinterpret_cast<const ulonglong2*>(s_mean + n * IN_CH);
        #pragma unroll
        for (int kk = 0; kk < IN_CH / 4; kk++) {
            ulonglong2 mv = mrow[kk];             // LDS.128, broadcast
            fma2(acc2, mv.x, w2[2 * kk + 0]);
            fma2(acc2, mv.y, w2[2 * kk + 1]);
        }
        float lo, hi;
        asm("mov.b64 {%0, %1}, %2;" : "=f"(lo), "=f"(hi) : "l"(acc2));
        const int node = node0 + n;
        if (node < N_NODES) {
            out[(size_t)node * HID_CH + o] = lo + hi;
        }
    }
}

// ---------------------------------------------------------------------------
extern "C" void kernel_launch(void* const* d_in, const int* in_sizes, int n_in,
                              void* d_out, int out_size) {
    const float* x  = (const float*)d_in[0];      // [50000, 64] fp32
    const int*   ei = (const int*)d_in[1];        // [2, 800000] int32
    const float* W  = (const float*)d_in[2];      // [128, 64] fp32
    float* out = (float*)d_out;                   // [50000, 128] fp32

    k_bucket<<<(N_EDGES + 255) / 256, 256>>>(ei);
    k_fused<<<(N_NODES + NPB - 1) / NPB, 128>>>(x, W, out);
}